// round 8
// baseline (speedup 1.0000x reference)
#include <cuda_runtime.h>
#include <cuda_fp16.h>
#include <cstdint>
#include <cstddef>

#define T_TOK 16384
#define D_DIM 1024
#define H_DIM 4096
#define E_NUM 8
#define LN_EPS 1e-5f

// ---------------------------------------------------------------------------
// Scratch (device globals; allocations forbidden)
// ---------------------------------------------------------------------------
__device__ __half g_x16[(size_t)T_TOK * D_DIM];             // LN(x) fp16
__device__ __half g_We16[(size_t)E_NUM * H_DIM * D_DIM];    // experts fp16
__device__ __half g_Wc16[(size_t)D_DIM * H_DIM];            // Wc * 0.5 fp16
__device__ __half g_s0[(size_t)T_TOK * H_DIM];              // slot 0
__device__ __half g_s1[(size_t)T_TOK * H_DIM];              // slot 1
__device__ __half g_a16[(size_t)T_TOK * H_DIM];             // relu(s0+s1)
__device__ int            g_list[E_NUM][T_TOK];
__device__ unsigned char  g_slot[E_NUM][T_TOK];
__device__ int            g_count[E_NUM];

__global__ void zero_counts_kernel() {
    if (threadIdx.x < E_NUM) g_count[threadIdx.x] = 0;
}

// ---------------------------------------------------------------------------
// PTX helpers (sm_80-era features only; compiles under plain sm_100)
// ---------------------------------------------------------------------------
__device__ __forceinline__ uint32_t smem_u32(const void* p) {
    uint32_t a;
    asm("{ .reg .u64 t; cvta.to.shared.u64 t, %1; cvt.u32.u64 %0, t; }"
        : "=r"(a) : "l"(p));
    return a;
}
__device__ __forceinline__ void cp_async16(uint32_t dst, const void* src) {
    asm volatile("cp.async.cg.shared.global [%0], [%1], 16;"
                 :: "r"(dst), "l"(src));
}
#define CP_COMMIT() asm volatile("cp.async.commit_group;")
#define CP_WAIT0()  asm volatile("cp.async.wait_group 0;")
#define CP_WAIT1()  asm volatile("cp.async.wait_group 1;")

#define LDSM4(r0, r1, r2, r3, addr) \
    asm volatile("ldmatrix.sync.aligned.m8n8.x4.shared.b16 {%0,%1,%2,%3}, [%4];" \
                 : "=r"(r0), "=r"(r1), "=r"(r2), "=r"(r3) : "r"(addr))

#define MMA16(d, a, b0, b1) \
    asm volatile("mma.sync.aligned.m16n8k16.row.col.f32.f16.f16.f32 " \
                 "{%0,%1,%2,%3}, {%4,%5,%6,%7}, {%8,%9}, {%0,%1,%2,%3};" \
                 : "+f"((d)[0]), "+f"((d)[1]), "+f"((d)[2]), "+f"((d)[3]) \
                 : "r"((a)[0]), "r"((a)[1]), "r"((a)[2]), "r"((a)[3]), \
                   "r"(b0), "r"(b1))

// ---------------------------------------------------------------------------
// fp32 -> fp16 weight conversion (0.5/top_k folded exactly into Wc)
// ---------------------------------------------------------------------------
__global__ void conv_We_kernel(const float* __restrict__ src) {
    size_t i = (size_t)blockIdx.x * blockDim.x + threadIdx.x;
    float4 v = ((const float4*)src)[i];
    __half2 a = __floats2half2_rn(v.x, v.y);
    __half2 b = __floats2half2_rn(v.z, v.w);
    uint2 u; u.x = *(uint32_t*)&a; u.y = *(uint32_t*)&b;
    ((uint2*)g_We16)[i] = u;
}
__global__ void conv_Wc_kernel(const float* __restrict__ src) {
    size_t i = (size_t)blockIdx.x * blockDim.x + threadIdx.x;
    float4 v = ((const float4*)src)[i];
    __half2 a = __floats2half2_rn(v.x * 0.5f, v.y * 0.5f);
    __half2 b = __floats2half2_rn(v.z * 0.5f, v.w * 0.5f);
    uint2 u; u.x = *(uint32_t*)&a; u.y = *(uint32_t*)&b;
    ((uint2*)g_Wc16)[i] = u;
}

// ---------------------------------------------------------------------------
// combine: g_a16 = relu(s0 + s1)   (the *0.5 lives in Wc)
// ---------------------------------------------------------------------------
__device__ __forceinline__ uint32_t relu_add2(uint32_t a, uint32_t b) {
    __half2 z = __float2half2_rn(0.f);
    __half2 r = __hmax2(__hadd2(*(__half2*)&a, *(__half2*)&b), z);
    return *(uint32_t*)&r;
}
__global__ void combine_kernel() {
    size_t i = (size_t)blockIdx.x * blockDim.x + threadIdx.x;
    uint4 a = ((const uint4*)g_s0)[i];
    uint4 b = ((const uint4*)g_s1)[i];
    uint4 r;
    r.x = relu_add2(a.x, b.x); r.y = relu_add2(a.y, b.y);
    r.z = relu_add2(a.z, b.z); r.w = relu_add2(a.w, b.w);
    ((uint4*)g_a16)[i] = r;
}

// ---------------------------------------------------------------------------
// Kernel 1: LayerNorm + gating + top-2 routing. One block (256 thr) per token.
// ---------------------------------------------------------------------------
__global__ __launch_bounds__(256) void ln_gate_kernel(
    const float* __restrict__ x, const float* __restrict__ gamma,
    const float* __restrict__ beta, const float* __restrict__ Wg,
    const float* __restrict__ bg)
{
    const int t    = blockIdx.x;
    const int tid  = threadIdx.x;
    const int lane = tid & 31;
    const int warp = tid >> 5;

    __shared__ float s_red[16];
    __shared__ float s_stat[2];
    __shared__ float s_part[8][8];

    const float4* xt = (const float4*)(x + (size_t)t * D_DIM);
    float4 v = xt[tid];
    float s = v.x + v.y + v.z + v.w;
    float q = v.x * v.x + v.y * v.y + v.z * v.z + v.w * v.w;
    #pragma unroll
    for (int o = 16; o > 0; o >>= 1) {
        s += __shfl_xor_sync(0xffffffffu, s, o);
        q += __shfl_xor_sync(0xffffffffu, q, o);
    }
    if (lane == 0) { s_red[warp] = s; s_red[8 + warp] = q; }
    __syncthreads();
    if (tid == 0) {
        float ss = 0.f, qq = 0.f;
        #pragma unroll
        for (int w = 0; w < 8; ++w) { ss += s_red[w]; qq += s_red[8 + w]; }
        float mu  = ss * (1.0f / D_DIM);
        float var = qq * (1.0f / D_DIM) - mu * mu;
        s_stat[0] = mu;
        s_stat[1] = rsqrtf(var + LN_EPS);
    }
    __syncthreads();
    const float mu = s_stat[0], rs = s_stat[1];
    float4 g = ((const float4*)gamma)[tid];
    float4 b = ((const float4*)beta)[tid];
    v.x = (v.x - mu) * rs * g.x + b.x;
    v.y = (v.y - mu) * rs * g.y + b.y;
    v.z = (v.z - mu) * rs * g.z + b.z;
    v.w = (v.w - mu) * rs * g.w + b.w;
    {
        __half2 h01 = __floats2half2_rn(v.x, v.y);
        __half2 h23 = __floats2half2_rn(v.z, v.w);
        uint2 u; u.x = *(uint32_t*)&h01; u.y = *(uint32_t*)&h23;
        ((uint2*)(g_x16 + (size_t)t * D_DIM))[tid] = u;
    }

    // gating partials from registers (Wg is 32KB, L1-resident)
    float p[E_NUM];
    #pragma unroll
    for (int e = 0; e < E_NUM; ++e) {
        float4 w = ((const float4*)(Wg + (size_t)e * D_DIM))[tid];
        p[e] = v.x * w.x + v.y * w.y + v.z * w.z + v.w * w.w;
    }
    #pragma unroll
    for (int o = 16; o > 0; o >>= 1) {
        #pragma unroll
        for (int e = 0; e < E_NUM; ++e)
            p[e] += __shfl_xor_sync(0xffffffffu, p[e], o);
    }
    if (lane == 0) {
        #pragma unroll
        for (int e = 0; e < E_NUM; ++e) s_part[warp][e] = p[e];
    }
    __syncthreads();

    if (tid == 0) {
        float best = -1e30f, sec = -1e30f;
        int bi = 0, si = 0;
        #pragma unroll
        for (int e = 0; e < E_NUM; ++e) {
            float l = bg[e];
            #pragma unroll
            for (int w = 0; w < 8; ++w) l += s_part[w][e];
            if (l > best) { sec = best; si = bi; best = l; bi = e; }
            else if (l > sec) { sec = l; si = e; }
        }
        int p0 = atomicAdd(&g_count[bi], 1);
        g_list[bi][p0] = t; g_slot[bi][p0] = 0;
        int p1 = atomicAdd(&g_count[si], 1);
        g_list[si][p1] = t; g_slot[si][p1] = 1;
    }
}

// ---------------------------------------------------------------------------
// GEMM geometry: BM=128, BN=256, BK=32 halves, PACKED conflict-free layout
// (logical rows 2r,2r+1 share one 128B line; chunk=(q|(m&1)<<2)^((m>>1)&7)).
// 8 warps in 2x4 grid, warp tile 64x64 -> per k16: 8 LDSM / 32 MMA (1:4).
// 2-stage cp.async pipeline: stage = A 8KB + B 16KB = 24KB; 2x24 = 48KB static.
// ---------------------------------------------------------------------------

// one pipeline stage of compute: K=32 = 2 x k16; 4 A-frags x 8 B-cols
#define GEMM_STAGE_COMPUTE(sAb, sBb)                                           \
    _Pragma("unroll")                                                          \
    for (int ks = 0; ks < 2; ++ks) {                                           \
        uint32_t af[4][4];                                                     \
        const uint32_t qa = ((uint32_t)ks << 1) + hiA;                         \
        const uint32_t ca = ((qa | a_h) ^ a_sw) << 4;                          \
        _Pragma("unroll")                                                      \
        for (int mt = 0; mt < 4; ++mt)                                         \
            LDSM4(af[mt][0], af[mt][1], af[mt][2], af[mt][3],                  \
                  (sAb) + a_phys + mt * 1024 + ca);                            \
        const uint32_t qb = ((uint32_t)ks << 1) + hiB;                         \
        const uint32_t cb = ((qb | b_h) ^ b_sw) << 4;                          \
        _Pragma("unroll")                                                      \
        for (int np = 0; np < 4; ++np) {                                       \
            uint32_t bf[4];                                                    \
            LDSM4(bf[0], bf[1], bf[2], bf[3],                                  \
                  (sBb) + b_phys + np * 1024 + cb);                            \
            _Pragma("unroll")                                                  \
            for (int mt = 0; mt < 4; ++mt) {                                   \
                MMA16(acc[mt][np * 2],     af[mt], bf[0], bf[1]);              \
                MMA16(acc[mt][np * 2 + 1], af[mt], bf[2], bf[3]);              \
            }                                                                  \
        }                                                                      \
    }

// ---------------------------------------------------------------------------
// Kernel 2: grouped expert GEMM. grid (H/256, T/128, E); tiles past count exit.
// ---------------------------------------------------------------------------
__global__ __launch_bounds__(256, 1) void expert_mm_kernel(const float* __restrict__ be)
{
    const int e   = blockIdx.z;
    const int cnt = g_count[e];
    const int m0  = blockIdx.y * 128;
    if (m0 >= cnt) return;
    const int n0  = blockIdx.x * 256;

    __shared__ __align__(1024) char smem[49152];
    const uint32_t sb = smem_u32(smem);
    // stage s: A at sb + s*24576, B at sb + s*24576 + 8192

    const int tid  = threadIdx.x;
    const int wid  = tid >> 5;
    const int lane = tid & 31;

    // ---- loader: thread = (logical row rb (+64k), 16B chunk q) ----
    const int rb = tid >> 2;          // 0..63
    const int q  = tid & 3;           // 0..3
    const uint32_t sw0 = (uint32_t)((rb >> 1) * 128 +
        ((((uint32_t)q | ((rb & 1) << 2)) ^ ((rb >> 1) & 7)) << 4));
    const int mA0 = m0 + rb, mA1 = m0 + rb + 64;
    const __half* aptr0 = g_x16 + (size_t)g_list[e][mA0 < cnt ? mA0 : 0] * D_DIM + q * 8;
    const __half* aptr1 = g_x16 + (size_t)g_list[e][mA1 < cnt ? mA1 : 0] * D_DIM + q * 8;
    const __half* bptr0 = g_We16 + ((size_t)e * H_DIM + n0 + rb) * D_DIM + q * 8;
    const __half* bptr1 = bptr0 + (size_t)64  * D_DIM;
    const __half* bptr2 = bptr0 + (size_t)128 * D_DIM;
    const __half* bptr3 = bptr0 + (size_t)192 * D_DIM;

    // ---- compute setup: warp grid 2x4, warp tile 64x64 ----
    const int wm = wid >> 2, wn = wid & 3;
    const uint32_t hiA = lane >> 4;
    const uint32_t hiB = (lane >> 3) & 1;
    const uint32_t mr = (uint32_t)(wm * 64 + (lane & 15));
    const uint32_t a_phys = (mr >> 1) * 128;
    const uint32_t a_h    = (mr & 1) << 2;
    const uint32_t a_sw   = (mr >> 1) & 7;
    const uint32_t nr = (uint32_t)(wn * 64 + ((lane >> 4) << 3) + (lane & 7));
    const uint32_t b_phys = (nr >> 1) * 128;
    const uint32_t b_h    = (nr & 1) << 2;
    const uint32_t b_sw   = (nr >> 1) & 7;

    float acc[4][8][4];
    #pragma unroll
    for (int i = 0; i < 4; ++i)
        #pragma unroll
        for (int j = 0; j < 8; ++j)
            #pragma unroll
            for (int k = 0; k < 4; ++k) acc[i][j][k] = 0.f;

    const int NC = D_DIM / 32;  // 32 chunks
    // prologue: stages 0, 1
    #pragma unroll
    for (int s = 0; s < 2; ++s) {
        const uint32_t sA = sb + s * 24576, sB = sA + 8192;
        cp_async16(sA + sw0,         aptr0 + s * 32);
        cp_async16(sA + sw0 + 4096,  aptr1 + s * 32);
        cp_async16(sB + sw0,         bptr0 + s * 32);
        cp_async16(sB + sw0 + 4096,  bptr1 + s * 32);
        cp_async16(sB + sw0 + 8192,  bptr2 + s * 32);
        cp_async16(sB + sw0 + 12288, bptr3 + s * 32);
        CP_COMMIT();
    }

    #pragma unroll 1
    for (int i = 0; i < NC; ++i) {
        if (i + 1 < NC) { CP_WAIT1(); } else { CP_WAIT0(); }
        __syncthreads();
        const uint32_t sAb = sb + (i & 1) * 24576, sBb = sAb + 8192;
        GEMM_STAGE_COMPUTE(sAb, sBb);
        __syncthreads();
        if (i + 2 < NC) {
            const uint32_t sA = sAb, sB = sBb;   // refill the buffer just freed
            cp_async16(sA + sw0,         aptr0 + (i + 2) * 32);
            cp_async16(sA + sw0 + 4096,  aptr1 + (i + 2) * 32);
            cp_async16(sB + sw0,         bptr0 + (i + 2) * 32);
            cp_async16(sB + sw0 + 4096,  bptr1 + (i + 2) * 32);
            cp_async16(sB + sw0 + 8192,  bptr2 + (i + 2) * 32);
            cp_async16(sB + sw0 + 12288, bptr3 + (i + 2) * 32);
            CP_COMMIT();
        }
    }

    // ---- epilogue: + bias, fp16, scatter to slot buffers ----
    const int colb = n0 + wn * 64 + 2 * (lane & 3);
    const float* bbias = be + (size_t)e * H_DIM + colb;
    float2 bv[8];
    #pragma unroll
    for (int nf = 0; nf < 8; ++nf)
        bv[nf] = *(const float2*)(bbias + nf * 8);

    #pragma unroll
    for (int mt = 0; mt < 4; ++mt) {
        #pragma unroll
        for (int h = 0; h < 2; ++h) {
            const int m = m0 + wm * 64 + mt * 16 + h * 8 + (lane >> 2);
            if (m < cnt) {
                const int tok = g_list[e][m];
                __half* dst = (g_slot[e][m] ? g_s1 : g_s0)
                              + (size_t)tok * H_DIM + colb;
                #pragma unroll
                for (int nf = 0; nf < 8; ++nf) {
                    __half2 hv = __floats2half2_rn(acc[mt][nf][2 * h]     + bv[nf].x,
                                                   acc[mt][nf][2 * h + 1] + bv[nf].y);
                    *(__half2*)(dst + nf * 8) = hv;
                }
            }
        }
    }
}

// ---------------------------------------------------------------------------
// Kernel 3: condense GEMM. out = x_in + A(g_a16) @ (0.5*Wc)^T + bc.
// grid (D/256, T/128).
// ---------------------------------------------------------------------------
__global__ __launch_bounds__(256, 1) void condense_mm_kernel(
    const float* __restrict__ bc, const float* __restrict__ xin,
    float* __restrict__ out)
{
    const int n0 = blockIdx.x * 256;
    const int m0 = blockIdx.y * 128;

    __shared__ __align__(1024) char smem[49152];
    const uint32_t sb = smem_u32(smem);

    const int tid  = threadIdx.x;
    const int wid  = tid >> 5;
    const int lane = tid & 31;

    const int rb = tid >> 2;
    const int q  = tid & 3;
    const uint32_t sw0 = (uint32_t)((rb >> 1) * 128 +
        ((((uint32_t)q | ((rb & 1) << 2)) ^ ((rb >> 1) & 7)) << 4));
    const __half* aptr0 = g_a16 + (size_t)(m0 + rb) * H_DIM + q * 8;
    const __half* aptr1 = aptr0 + (size_t)64 * H_DIM;
    const __half* bptr0 = g_Wc16 + (size_t)(n0 + rb) * H_DIM + q * 8;
    const __half* bptr1 = bptr0 + (size_t)64  * H_DIM;
    const __half* bptr2 = bptr0 + (size_t)128 * H_DIM;
    const __half* bptr3 = bptr0 + (size_t)192 * H_DIM;

    const int wm = wid >> 2, wn = wid & 3;
    const uint32_t hiA = lane >> 4;
    const uint32_t hiB = (lane >> 3) & 1;
    const uint32_t mr = (uint32_t)(wm * 64 + (lane & 15));
    const uint32_t a_phys = (mr >> 1) * 128;
    const uint32_t a_h    = (mr & 1) << 2;
    const uint32_t a_sw   = (mr >> 1) & 7;
    const uint32_t nr = (uint32_t)(wn * 64 + ((lane >> 4) << 3) + (lane & 7));
    const uint32_t b_phys = (nr >> 1) * 128;
    const uint32_t b_h    = (nr & 1) << 2;
    const uint32_t b_sw   = (nr >> 1) & 7;

    float acc[4][8][4];
    #pragma unroll
    for (int i = 0; i < 4; ++i)
        #pragma unroll
        for (int j = 0; j < 8; ++j)
            #pragma unroll
            for (int k = 0; k < 4; ++k) acc[i][j][k] = 0.f;

    const int NC = H_DIM / 32;  // 128 chunks
    #pragma unroll
    for (int s = 0; s < 2; ++s) {
        const uint32_t sA = sb + s * 24576, sB = sA + 8192;
        cp_async16(sA + sw0,         aptr0 + s * 32);
        cp_async16(sA + sw0 + 4096,  aptr1 + s * 32);
        cp_async16(sB + sw0,         bptr0 + s * 32);
        cp_async16(sB + sw0 + 4096,  bptr1 + s * 32);
        cp_async16(sB + sw0 + 8192,  bptr2 + s * 32);
        cp_async16(sB + sw0 + 12288, bptr3 + s * 32);
        CP_COMMIT();
    }

    #pragma unroll 1
    for (int i = 0; i < NC; ++i) {
        if (i + 1 < NC) { CP_WAIT1(); } else { CP_WAIT0(); }
        __syncthreads();
        const uint32_t sAb = sb + (i & 1) * 24576, sBb = sAb + 8192;
        GEMM_STAGE_COMPUTE(sAb, sBb);
        __syncthreads();
        if (i + 2 < NC) {
            const uint32_t sA = sAb, sB = sBb;
            cp_async16(sA + sw0,         aptr0 + (i + 2) * 32);
            cp_async16(sA + sw0 + 4096,  aptr1 + (i + 2) * 32);
            cp_async16(sB + sw0,         bptr0 + (i + 2) * 32);
            cp_async16(sB + sw0 + 4096,  bptr1 + (i + 2) * 32);
            cp_async16(sB + sw0 + 8192,  bptr2 + (i + 2) * 32);
            cp_async16(sB + sw0 + 12288, bptr3 + (i + 2) * 32);
            CP_COMMIT();
        }
    }

    // ---- epilogue: out = x_in + y + bc ----
    const int colb = n0 + wn * 64 + 2 * (lane & 3);
    float2 bv[8];
    #pragma unroll
    for (int nf = 0; nf < 8; ++nf)
        bv[nf] = *(const float2*)(bc + colb + nf * 8);

    #pragma unroll
    for (int mt = 0; mt < 4; ++mt) {
        #pragma unroll
        for (int h = 0; h < 2; ++h) {
            const int trow = m0 + wm * 64 + mt * 16 + h * 8 + (lane >> 2);
            const float* xr = xin + (size_t)trow * D_DIM + colb;
            float* orow     = out + (size_t)trow * D_DIM + colb;
            #pragma unroll
            for (int nf = 0; nf < 8; ++nf) {
                float2 xv = *(const float2*)(xr + nf * 8);
                float2 o;
                o.x = xv.x + bv[nf].x + acc[mt][nf][2 * h];
                o.y = xv.y + bv[nf].y + acc[mt][nf][2 * h + 1];
                *(float2*)(orow + nf * 8) = o;
            }
        }
    }
}

// ---------------------------------------------------------------------------
// Launch: kernel launches ONLY (no attribute calls, no dynamic smem)
// ---------------------------------------------------------------------------
extern "C" void kernel_launch(void* const* d_in, const int* in_sizes, int n_in,
                              void* d_out, int out_size) {
    (void)in_sizes; (void)n_in; (void)out_size;
    const float* x     = (const float*)d_in[0];
    const float* gamma = (const float*)d_in[1];
    const float* beta  = (const float*)d_in[2];
    const float* Wg    = (const float*)d_in[3];
    const float* bg    = (const float*)d_in[4];
    const float* We    = (const float*)d_in[5];
    const float* be    = (const float*)d_in[6];
    const float* Wc    = (const float*)d_in[7];
    const float* bc    = (const float*)d_in[8];
    float* out = (float*)d_out;

    zero_counts_kernel<<<1, 32>>>();
    conv_We_kernel<<<(E_NUM * H_DIM * D_DIM / 4) / 256, 256>>>(We);
    conv_Wc_kernel<<<(D_DIM * H_DIM / 4) / 256, 256>>>(Wc);
    ln_gate_kernel<<<T_TOK, 256>>>(x, gamma, beta, Wg, bg);

    dim3 g1(H_DIM / 256, T_TOK / 128, E_NUM);   // (16, 128, 8); most CTAs exit
    expert_mm_kernel<<<g1, 256>>>(be);

    combine_kernel<<<((size_t)T_TOK * H_DIM / 8) / 256, 256>>>();

    dim3 g2(D_DIM / 256, T_TOK / 128);          // (4, 128)
    condense_mm_kernel<<<g2, 256>>>(bc, x, out);
}